// round 10
// baseline (speedup 1.0000x reference)
#include <cuda_runtime.h>
#include <math.h>

#define B_  32
#define L_  128
#define D_  300
#define H_  128
#define G4  512
#define E_  34
#define A_  36
#define NH  256
#define N_  4096    // B_*L_

// ---------------- scratch (device globals; no allocations) ----------------
__device__ float  d_xp2[2][N_][G4];        // [dir][n][gate-row]
__device__ float4 d_wt[2][32][G4];         // packed W_hh: [dir][k4][row]
__device__ float  d_hidden[N_*NH];         // [n][2H]
__device__ float  d_base[N_*A_];
__device__ float  d_trig[N_*A_];
__device__ int    d_evpred[N_];

__device__ __forceinline__ float sigf(float x){ return 1.f/(1.f + __expf(-x)); }
__device__ __forceinline__ float tanhfast(float x){ return 2.f/(1.f + __expf(-2.f*x)) - 1.f; }

__device__ __forceinline__ void ffma2(unsigned long long &d, unsigned long long a, unsigned long long b){
    asm("fma.rn.f32x2 %0, %1, %2, %0;" : "+l"(d) : "l"(a), "l"(b));
}
__device__ __forceinline__ unsigned long long splat2(float a){
    unsigned long long d; asm("mov.b64 %0, {%1, %1};" : "=l"(d) : "f"(a)); return d;
}
__device__ __forceinline__ float2 unpack2(unsigned long long a){
    float2 r; asm("mov.b64 {%0, %1}, %2;" : "=f"(r.x), "=f"(r.y) : "l"(a)); return r;
}

struct __align__(16) ull2 { unsigned long long x, y; };

// ---------------- K0: pack W_hh into [dir][k4][row] float4 ----------------
__global__ void k0_pack(const float* __restrict__ whhf, const float* __restrict__ whhb){
    int idx = blockIdx.x*256 + threadIdx.x;
    if (idx >= 2*G4*32) return;
    int dir = idx >> 14;
    int rem = idx & 16383;
    int r   = rem >> 5;
    int k4  = rem & 31;
    const float* w = (dir ? whhb : whhf) + (size_t)r*H_ + k4*4;
    d_wt[dir][k4][r] = make_float4(w[0], w[1], w[2], w[3]);
}

// ---------------- K1: emb gather + input projection SGEMM (128x128x8, 8x8 micro, f32x2) ----------------
__global__ void __launch_bounds__(256) k1_gemm(const int* __restrict__ ids, const float* __restrict__ emb,
                        const float* __restrict__ wf, const float* __restrict__ wb,
                        const float* __restrict__ bihf, const float* __restrict__ bhhf,
                        const float* __restrict__ bihb, const float* __restrict__ bhhb)
{
    __shared__ float As[8][132];
    __shared__ float Bs[8][132];
    int tid = threadIdx.x;
    int n0 = blockIdx.y * 128;
    int c0 = blockIdx.x * 128;
    int tx = tid & 15, ty = tid >> 4;

    int lrow = tid >> 1;
    int lkh  = (tid & 1) * 4;

    const float* a_src = emb + (size_t)ids[n0 + lrow] * D_ + lkh;
    int gcol = c0 + lrow;
    const float* b_src = ((gcol < 512) ? (wf + (size_t)gcol * D_)
                                       : (wb + (size_t)(gcol - 512) * D_)) + lkh;

    unsigned long long acc2[8][4];
    #pragma unroll
    for (int i=0;i<8;i++)
        #pragma unroll
        for (int p=0;p<4;p++) acc2[i][p]=0ull;

    for (int k0 = 0; k0 < 304; k0 += 8){
        float av[4], bv[4];
        if (k0 + lkh + 3 < D_){
            float4 a4 = *(const float4*)(a_src + k0);
            float4 b4 = *(const float4*)(b_src + k0);
            av[0]=a4.x; av[1]=a4.y; av[2]=a4.z; av[3]=a4.w;
            bv[0]=b4.x; bv[1]=b4.y; bv[2]=b4.z; bv[3]=b4.w;
        } else {
            #pragma unroll
            for (int u=0;u<4;u++){
                int k = k0 + lkh + u;
                av[u] = (k < D_) ? a_src[k0 + u] : 0.f;
                bv[u] = (k < D_) ? b_src[k0 + u] : 0.f;
            }
        }
        #pragma unroll
        for (int u=0;u<4;u++){ As[lkh+u][lrow] = av[u]; Bs[lkh+u][lrow] = bv[u]; }
        __syncthreads();
        #pragma unroll
        for (int k=0;k<8;k++){
            float4 a0 = *(const float4*)&As[k][ty*8];
            float4 a1 = *(const float4*)&As[k][ty*8+4];
            ull2 b0 = *(const ull2*)&Bs[k][tx*8];
            ull2 b1 = *(const ull2*)&Bs[k][tx*8+4];
            float af[8];
            af[0]=a0.x;af[1]=a0.y;af[2]=a0.z;af[3]=a0.w;
            af[4]=a1.x;af[5]=a1.y;af[6]=a1.z;af[7]=a1.w;
            #pragma unroll
            for (int i=0;i<8;i++){
                unsigned long long asp = splat2(af[i]);
                ffma2(acc2[i][0], asp, b0.x);
                ffma2(acc2[i][1], asp, b0.y);
                ffma2(acc2[i][2], asp, b1.x);
                ffma2(acc2[i][3], asp, b1.y);
            }
        }
        __syncthreads();
    }
    int colb = c0 + tx*8;
    int dir  = colb >> 9;
    int jb   = colb & 511;
    float bias[8];
    #pragma unroll
    for (int j=0;j<8;j++){
        int jj = jb + j;
        bias[j] = dir ? (bihb[jj]+bhhb[jj]) : (bihf[jj]+bhhf[jj]);
    }
    #pragma unroll
    for (int i=0;i<8;i++){
        int n = n0 + ty*8 + i;
        float* dst = &d_xp2[dir][n][jb];
        float2 p0 = unpack2(acc2[i][0]);
        float2 p1 = unpack2(acc2[i][1]);
        float2 p2 = unpack2(acc2[i][2]);
        float2 p3 = unpack2(acc2[i][3]);
        float4 v0 = make_float4(p0.x+bias[0], p0.y+bias[1], p1.x+bias[2], p1.y+bias[3]);
        float4 v1 = make_float4(p2.x+bias[4], p2.y+bias[5], p3.x+bias[6], p3.y+bias[7]);
        *(float4*)(dst)   = v0;
        *(float4*)(dst+4) = v1;
    }
}

// ---------------- K2: BiLSTM, 64 blocks x 1024 thr, thread=(j,gate,k-half), shfl combine ----------------
// 12 of 16 weight-ull2 in registers, 4 in a private SMEM slot (no spill). ONE barrier/step.
// Lane group of 8: {i0,i1,f0,f1,g0,g1,o0,o1}; xor1 merges k-halves, xor2/xor4/xor4 give
// the f-lane (g8==2) z_i, z_o, z_g. f-lane owns c, writes h into double-buffered h_s.
__global__ void __launch_bounds__(1024, 1) k2_lstm()
{
    extern __shared__ float smem2[];
    float4* sww = (float4*)smem2;              // [4][1024] float4 (private per-thread slots)
    float*  h_s = smem2 + 4*1024*4;            // [2][128]

    int bid = blockIdx.x;
    int dir = bid >> 5;
    int b   = bid & 31;
    int t   = threadIdx.x;
    int j   = t >> 3;
    int g8  = t & 7;
    int gate= g8 >> 1;         // 0=i,1=f,2=g,3=o
    int kh  = g8 & 1;
    int r   = gate*128 + j;

    ull2 w[12];
    #pragma unroll
    for (int q=0; q<12; q++)
        w[q] = *(const ull2*)&d_wt[dir][kh*16 + q][r];
    #pragma unroll
    for (int q=0; q<4; q++)
        sww[q*1024 + t] = *(const float4*)&d_wt[dir][kh*16 + 12 + q][r];

    if (t < 256) h_s[t] = 0.f;
    __syncthreads();

    const float* xpd = &d_xp2[dir][0][0];
    bool is_f = (g8 == 2);
    float cr = 0.f;

    int t_out0 = dir ? (L_-1) : 0;
    float xcur = (kh==0) ? xpd[(size_t)(b*L_ + t_out0)*G4 + r] : 0.f;

    for (int s = 0; s < L_; s++){
        int p = s & 1;
        int t_out = dir ? (L_-1-s) : s;
        int n0 = b*L_ + t_out;
        float xnext = 0.f;
        if (kh==0 && s+1 < L_){
            int t_o2 = dir ? (L_-2-s) : (s+1);
            xnext = xpd[(size_t)(b*L_ + t_o2)*G4 + r];
        }
        const float* hb = h_s + p*128 + kh*64;

        unsigned long long aA=0ull, aB=0ull;
        #pragma unroll
        for (int q=0; q<12; q+=2){
            ull2 h0 = *(const ull2*)(hb + q*4);
            ull2 h1 = *(const ull2*)(hb + q*4 + 4);
            ffma2(aA, w[q].x,   h0.x); ffma2(aA, w[q].y,   h0.y);
            ffma2(aB, w[q+1].x, h1.x); ffma2(aB, w[q+1].y, h1.y);
        }
        #pragma unroll
        for (int q=0; q<4; q+=2){
            ull2 ws0 = *(const ull2*)&sww[q*1024 + t];
            ull2 ws1 = *(const ull2*)&sww[(q+1)*1024 + t];
            ull2 h0 = *(const ull2*)(hb + (12+q)*4);
            ull2 h1 = *(const ull2*)(hb + (12+q)*4 + 4);
            ffma2(aA, ws0.x, h0.x); ffma2(aA, ws0.y, h0.y);
            ffma2(aB, ws1.x, h1.x); ffma2(aB, ws1.y, h1.y);
        }
        float2 fa = unpack2(aA), fb = unpack2(aB);
        float part = (fa.x + fa.y) + (fb.x + fb.y) + xcur;
        float z  = part + __shfl_xor_sync(0xffffffffu, part, 1);
        float s1 = __shfl_xor_sync(0xffffffffu, z, 2);
        float s2 = __shfl_xor_sync(0xffffffffu, z, 4);
        float s3 = __shfl_xor_sync(0xffffffffu, s1, 4);
        if (is_f){
            // lane f: z=z_f, s1=z_i, s2=z_o, s3=z_g
            cr = sigf(z)*cr + sigf(s1)*tanhfast(s3);
            float h = sigf(s2)*tanhfast(cr);
            h_s[(p^1)*128 + j] = h;
            d_hidden[(size_t)n0*NH + dir*H_ + j] = h;
        }
        xcur = xnext;
        __syncthreads();
    }
}

// ---------------- K3: fused heads GEMM, single-stage SMEM + event argmax ----------------
__global__ void __launch_bounds__(256) k3_heads(const float* __restrict__ evw, const float* __restrict__ evb,
                         const float* __restrict__ argw, const float* __restrict__ argb,
                         float* __restrict__ out_ev)
{
    extern __shared__ float sm3[];
    float* hsT = sm3;              // [256][68]  hsT[k*68 + r]
    float* wT  = hsT + 256*68;     // [256][56]  wT[k*56 + cl]
    float* evs = wT + 256*56;      // [64][34]

    int rb = (blockIdx.x >> 1) * 64;
    int cg = blockIdx.x & 1;
    int cbase = cg * 53;
    int tid = threadIdx.x;
    int tx = tid & 15, ty = tid >> 4;

    {
        int r  = tid & 63;
        int kc = (tid >> 6) * 64;
        const float4* src = (const float4*)&d_hidden[(size_t)(rb+r)*NH + kc];
        #pragma unroll
        for (int m=0;m<16;m++){
            float4 v = src[m];
            int k = kc + m*4;
            hsT[(k+0)*68 + r] = v.x;
            hsT[(k+1)*68 + r] = v.y;
            hsT[(k+2)*68 + r] = v.z;
            hsT[(k+3)*68 + r] = v.w;
        }
    }
    {
        int cl = tid & 63;
        int kc = (tid >> 6) * 64;
        if (cl < 53){
            int c = cbase + cl;
            const float* srcp = (c < 34) ? (evw + (size_t)c*256)
                              : (c < 70) ? (argw + (size_t)(c-34)*545)
                                         : (argw + (size_t)(c-70)*545 + 256);
            #pragma unroll 8
            for (int m=0;m<64;m++){
                wT[(kc+m)*56 + cl] = __ldg(srcp + kc + m);
            }
        }
    }
    __syncthreads();

    unsigned long long acc[4][2];
    #pragma unroll
    for (int i=0;i<4;i++){ acc[i][0]=0ull; acc[i][1]=0ull; }

    #pragma unroll 4
    for (int k=0;k<256;k++){
        float4 hv = *(const float4*)&hsT[k*68 + ty*4];
        ull2   wv = *(const ull2*)&wT[k*56 + tx*4];
        unsigned long long h0 = splat2(hv.x);
        unsigned long long h1 = splat2(hv.y);
        unsigned long long h2 = splat2(hv.z);
        unsigned long long h3 = splat2(hv.w);
        ffma2(acc[0][0], h0, wv.x); ffma2(acc[0][1], h0, wv.y);
        ffma2(acc[1][0], h1, wv.x); ffma2(acc[1][1], h1, wv.y);
        ffma2(acc[2][0], h2, wv.x); ffma2(acc[2][1], h2, wv.y);
        ffma2(acc[3][0], h3, wv.x); ffma2(acc[3][1], h3, wv.y);
    }

    #pragma unroll
    for (int i=0;i<4;i++){
        int n = rb + ty*4 + i;
        float v[4];
        float2 p0 = unpack2(acc[i][0]);
        float2 p1 = unpack2(acc[i][1]);
        v[0]=p0.x; v[1]=p0.y; v[2]=p1.x; v[3]=p1.y;
        #pragma unroll
        for (int jj=0;jj<4;jj++){
            int cl = tx*4 + jj;
            if (cl < 53){
                int c = cbase + cl;
                if (c < 34){
                    float val = v[jj] + evb[c];
                    out_ev[(size_t)n*E_ + c] = val;
                    evs[(ty*4+i)*34 + c] = val;
                } else if (c < 70){
                    int a = c - 34;
                    d_base[(size_t)n*A_ + a] = v[jj] + argb[a];
                } else {
                    int a = c - 70;
                    d_trig[(size_t)n*A_ + a] = v[jj];
                }
            }
        }
    }
    if (cg == 0){
        __syncthreads();
        if (tid < 64){
            float best = evs[tid*34]; int bi = 0;
            #pragma unroll
            for (int e=1; e<E_; e++){ float vv = evs[tid*34 + e]; if (vv > best){ best = vv; bi = e; } }
            d_evpred[rb + tid] = bi;
        }
    }
}

// ---------------- K5: per-(b,l) g-scan + fused broadcast output (trig prefetch) ----------------
__global__ void k5_scan(const float* __restrict__ argw, float* __restrict__ out_args){
    __shared__ float w3[33][36];
    int bid = blockIdx.x;
    int b = bid >> 7, l = bid & 127;
    int lane = threadIdx.x;
    for (int i = lane; i < 33*36; i += 32){
        int c = i / 36, a = i % 36;
        w3[c][a] = argw[(size_t)a*545 + 512 + c];
    }
    __syncwarp();
    int a0 = lane, a1 = lane + 32;
    bool v1ok = (a1 < A_);
    float base0 = d_base[(b*L_+l)*A_ + a0];
    float base1 = v1ok ? d_base[(b*L_+l)*A_ + a1] : 0.f;
    float gt0 = 0.f, gt1 = 0.f;
    unsigned long long mask = 0ull;
    const float* trigb = d_trig + (size_t)b*L_*A_;
    float* outb = out_args + (size_t)b*L_*L_*A_ + (size_t)l*A_;
    const int* evp = d_evpred + b*L_;
    float t0 = trigb[a0];
    float t1 = v1ok ? trigb[a1] : 0.f;
    for (int i = 0; i < L_; i++){
        float t0c = t0, t1c = t1;
        if (i+1 < L_){
            t0 = trigb[(i+1)*A_ + a0];
            t1 = v1ok ? trigb[(i+1)*A_ + a1] : 0.f;
        }
        float v0 = base0 + t0c + gt0;
        float v1 = base1 + t1c + gt1;
        float* orow = outb + (size_t)i*L_*A_;
        orow[a0] = v0;
        if (v1ok) orow[a1] = v1;
        float bv; int bi2;
        if (v1ok && v1 > v0){ bv = v1; bi2 = a1; } else { bv = v0; bi2 = a0; }
        #pragma unroll
        for (int off=16; off; off>>=1){
            float ov = __shfl_xor_sync(0xffffffffu, bv, off);
            int   oi = __shfl_xor_sync(0xffffffffu, bi2, off);
            if (ov > bv || (ov == bv && oi < bi2)){ bv = ov; bi2 = oi; }
        }
        int ev = evp[i];
        if (ev > 0 && bi2 > 0){
            int c = ev - 1;
            unsigned long long bit = 1ull << c;
            if (!(mask & bit)){
                mask |= bit;
                gt0 += w3[c][a0];
                if (v1ok) gt1 += w3[c][a1];
            }
        }
    }
}

// ---------------- launch ----------------
extern "C" void kernel_launch(void* const* d_in, const int* in_sizes, int n_in,
                              void* d_out, int out_size)
{
    const int*   ids  = (const int*)d_in[0];
    const float* emb  = (const float*)d_in[1];
    const float* wihf = (const float*)d_in[2];
    const float* whhf = (const float*)d_in[3];
    const float* bihf = (const float*)d_in[4];
    const float* bhhf = (const float*)d_in[5];
    const float* wihb = (const float*)d_in[6];
    const float* whhb = (const float*)d_in[7];
    const float* bihb = (const float*)d_in[8];
    const float* bhhb = (const float*)d_in[9];
    const float* evw  = (const float*)d_in[10];
    const float* evb  = (const float*)d_in[11];
    const float* argw = (const float*)d_in[12];
    const float* argb = (const float*)d_in[13];
    float* out = (float*)d_out;

    const int k2_smem = 4*1024*16 + 256*4;                  // 66560
    const int k3_smem = (256*68 + 256*56 + 64*34) * 4;      // 135680
    cudaFuncSetAttribute(k2_lstm, cudaFuncAttributeMaxDynamicSharedMemorySize, k2_smem);
    cudaFuncSetAttribute(k3_heads, cudaFuncAttributeMaxDynamicSharedMemorySize, k3_smem);

    k0_pack<<<128, 256>>>(whhf, whhb);                       // launch 1
    dim3 g1(8, 32);
    k1_gemm<<<g1, 256>>>(ids, emb, wihf, wihb, bihf, bhhf, bihb, bhhb); // launch 2
    k2_lstm<<<64, 1024, k2_smem>>>();                        // launch 3
    k3_heads<<<128, 256, k3_smem>>>(evw, evb, argw, argb, out); // launch 4 -> ncu-profiled
    k5_scan<<<N_, 32>>>(argw, out + N_*E_);
    (void)in_sizes; (void)n_in; (void)out_size;
}

// round 12
// speedup vs baseline: 1.0699x; 1.0699x over previous
#include <cuda_runtime.h>
#include <math.h>

#define B_  32
#define L_  128
#define D_  300
#define H_  128
#define G4  512
#define E_  34
#define A_  36
#define NH  256
#define N_  4096    // B_*L_

// ---------------- scratch (device globals; no allocations) ----------------
__device__ float  d_xp2[2][N_][G4];        // [dir][n][gate-row]
__device__ float4 d_wt[2][32][G4];         // packed W_hh: [dir][k4][row]
__device__ float  d_hidden[N_*NH];         // [n][2H]
__device__ float  d_base[N_*A_];
__device__ float  d_trig[N_*A_];
__device__ int    d_evpred[N_];
__device__ int    d_dummy;

__device__ __forceinline__ float sigf(float x){ return 1.f/(1.f + __expf(-x)); }
__device__ __forceinline__ float tanhfast(float x){ return 2.f/(1.f + __expf(-2.f*x)) - 1.f; }

__device__ __forceinline__ void ffma2(unsigned long long &d, unsigned long long a, unsigned long long b){
    asm("fma.rn.f32x2 %0, %1, %2, %0;" : "+l"(d) : "l"(a), "l"(b));
}
__device__ __forceinline__ unsigned long long splat2(float a){
    unsigned long long d; asm("mov.b64 %0, {%1, %1};" : "=l"(d) : "f"(a)); return d;
}
__device__ __forceinline__ float2 unpack2(unsigned long long a){
    float2 r; asm("mov.b64 {%0, %1}, %2;" : "=f"(r.x), "=f"(r.y) : "l"(a)); return r;
}

struct __align__(16) ull2 { unsigned long long x, y; };

// ---------------- K0: pack W_hh into [dir][k4][row] float4 ----------------
__global__ void k0_pack(const float* __restrict__ whhf, const float* __restrict__ whhb){
    int idx = blockIdx.x*256 + threadIdx.x;
    if (idx >= 2*G4*32) return;
    int dir = idx >> 14;
    int rem = idx & 16383;
    int r   = rem >> 5;
    int k4  = rem & 31;
    const float* w = (dir ? whhb : whhf) + (size_t)r*H_ + k4*4;
    d_wt[dir][k4][r] = make_float4(w[0], w[1], w[2], w[3]);
}

// ---------------- Kdummy: positions k2 into the ncu-profiled launch slot ----------------
__global__ void kdummy(){ if (threadIdx.x == 0) d_dummy = 1; }

// ---------------- K1: emb gather + input projection SGEMM (128x128x8, 8x8 micro, f32x2) ----------------
__global__ void __launch_bounds__(256) k1_gemm(const int* __restrict__ ids, const float* __restrict__ emb,
                        const float* __restrict__ wf, const float* __restrict__ wb,
                        const float* __restrict__ bihf, const float* __restrict__ bhhf,
                        const float* __restrict__ bihb, const float* __restrict__ bhhb)
{
    __shared__ float As[8][132];
    __shared__ float Bs[8][132];
    int tid = threadIdx.x;
    int n0 = blockIdx.y * 128;
    int c0 = blockIdx.x * 128;
    int tx = tid & 15, ty = tid >> 4;

    int lrow = tid >> 1;
    int lkh  = (tid & 1) * 4;

    const float* a_src = emb + (size_t)ids[n0 + lrow] * D_ + lkh;
    int gcol = c0 + lrow;
    const float* b_src = ((gcol < 512) ? (wf + (size_t)gcol * D_)
                                       : (wb + (size_t)(gcol - 512) * D_)) + lkh;

    unsigned long long acc2[8][4];
    #pragma unroll
    for (int i=0;i<8;i++)
        #pragma unroll
        for (int p=0;p<4;p++) acc2[i][p]=0ull;

    for (int k0 = 0; k0 < 304; k0 += 8){
        float av[4], bv[4];
        if (k0 + lkh + 3 < D_){
            float4 a4 = *(const float4*)(a_src + k0);
            float4 b4 = *(const float4*)(b_src + k0);
            av[0]=a4.x; av[1]=a4.y; av[2]=a4.z; av[3]=a4.w;
            bv[0]=b4.x; bv[1]=b4.y; bv[2]=b4.z; bv[3]=b4.w;
        } else {
            #pragma unroll
            for (int u=0;u<4;u++){
                int k = k0 + lkh + u;
                av[u] = (k < D_) ? a_src[k0 + u] : 0.f;
                bv[u] = (k < D_) ? b_src[k0 + u] : 0.f;
            }
        }
        #pragma unroll
        for (int u=0;u<4;u++){ As[lkh+u][lrow] = av[u]; Bs[lkh+u][lrow] = bv[u]; }
        __syncthreads();
        #pragma unroll
        for (int k=0;k<8;k++){
            float4 a0 = *(const float4*)&As[k][ty*8];
            float4 a1 = *(const float4*)&As[k][ty*8+4];
            ull2 b0 = *(const ull2*)&Bs[k][tx*8];
            ull2 b1 = *(const ull2*)&Bs[k][tx*8+4];
            float af[8];
            af[0]=a0.x;af[1]=a0.y;af[2]=a0.z;af[3]=a0.w;
            af[4]=a1.x;af[5]=a1.y;af[6]=a1.z;af[7]=a1.w;
            #pragma unroll
            for (int i=0;i<8;i++){
                unsigned long long asp = splat2(af[i]);
                ffma2(acc2[i][0], asp, b0.x);
                ffma2(acc2[i][1], asp, b0.y);
                ffma2(acc2[i][2], asp, b1.x);
                ffma2(acc2[i][3], asp, b1.y);
            }
        }
        __syncthreads();
    }
    int colb = c0 + tx*8;
    int dir  = colb >> 9;
    int jb   = colb & 511;
    float bias[8];
    #pragma unroll
    for (int j=0;j<8;j++){
        int jj = jb + j;
        bias[j] = dir ? (bihb[jj]+bhhb[jj]) : (bihf[jj]+bhhf[jj]);
    }
    #pragma unroll
    for (int i=0;i<8;i++){
        int n = n0 + ty*8 + i;
        float* dst = &d_xp2[dir][n][jb];
        float2 p0 = unpack2(acc2[i][0]);
        float2 p1 = unpack2(acc2[i][1]);
        float2 p2 = unpack2(acc2[i][2]);
        float2 p3 = unpack2(acc2[i][3]);
        float4 v0 = make_float4(p0.x+bias[0], p0.y+bias[1], p1.x+bias[2], p1.y+bias[3]);
        float4 v1 = make_float4(p2.x+bias[4], p2.y+bias[5], p3.x+bias[6], p3.y+bias[7]);
        *(float4*)(dst)   = v0;
        *(float4*)(dst+4) = v1;
    }
}

// ---------------- K2: BiLSTM, 64 blocks x 512 thr, thread = (j, k-quarter) ----------------
// All 4 gates of hidden unit j live in one thread (32 k's each): no cross-gate exchange.
// Weights: per gate 8 float4 = 4 in registers + 4 in SMEM private slot. 16 reg-f4 = 64 regs.
// Combine k-quarters with 2 shfl_xor; kq==0 lane owns c and writes h. ONE barrier/step.
__global__ void __launch_bounds__(512, 1) k2_lstm()
{
    extern __shared__ float smem2[];
    float4* sws = (float4*)smem2;              // [16][512] private slots: sws[idx*512 + t]
    float*  h_s = smem2 + 16*512*4;            // [2][128]

    int bid = blockIdx.x;
    int dir = bid >> 5;
    int b   = bid & 31;
    int t   = threadIdx.x;
    int j   = t >> 2;
    int kq  = t & 3;

    // weights: gate g row = g*128+j ; k4 chunks kq*8+q (q=0..7): q<4 regs, q>=4 SMEM
    ull2 wr[16];
    #pragma unroll
    for (int g=0; g<4; g++)
        #pragma unroll
        for (int q=0; q<4; q++)
            wr[g*4+q] = *(const ull2*)&d_wt[dir][kq*8+q][g*128+j];
    #pragma unroll
    for (int g=0; g<4; g++)
        #pragma unroll
        for (int q=0; q<4; q++)
            sws[(g*4+q)*512 + t] = *(const float4*)&d_wt[dir][kq*8+4+q][g*128+j];

    if (t < 256) h_s[t] = 0.f;
    __syncthreads();

    const float* xpd = &d_xp2[dir][0][0];
    bool lead = (kq == 0);
    float cr = 0.f;

    // x prefetch (lead lanes only)
    float x0=0.f, x1=0.f, x2=0.f, x3=0.f;
    {
        int t_out0 = dir ? (L_-1) : 0;
        size_t nb = (size_t)(b*L_ + t_out0)*G4 + j;
        if (lead){
            x0 = xpd[nb];
            x1 = xpd[nb + 128];
            x2 = xpd[nb + 256];
            x3 = xpd[nb + 384];
        }
    }

    for (int s = 0; s < L_; s++){
        int p = s & 1;
        int t_out = dir ? (L_-1-s) : s;
        int n0 = b*L_ + t_out;
        // prefetch next x
        float nx0=0.f, nx1=0.f, nx2=0.f, nx3=0.f;
        if (lead && s+1 < L_){
            int t_o2 = dir ? (L_-2-s) : (s+1);
            size_t nb = (size_t)(b*L_ + t_o2)*G4 + j;
            nx0 = xpd[nb];
            nx1 = xpd[nb + 128];
            nx2 = xpd[nb + 256];
            nx3 = xpd[nb + 384];
        }

        const float* hb = h_s + p*128 + kq*32;
        unsigned long long acc0=0ull, acc1=0ull, acc2a=0ull, acc3=0ull;
        // q-outer / gate-inner: one h chunk live at a time, 4 independent acc chains
        #pragma unroll
        for (int q=0; q<4; q++){
            ull2 hv = *(const ull2*)(hb + q*4);
            ffma2(acc0, wr[0*4+q].x, hv.x); ffma2(acc0, wr[0*4+q].y, hv.y);
            ffma2(acc1, wr[1*4+q].x, hv.x); ffma2(acc1, wr[1*4+q].y, hv.y);
            ffma2(acc2a, wr[2*4+q].x, hv.x); ffma2(acc2a, wr[2*4+q].y, hv.y);
            ffma2(acc3, wr[3*4+q].x, hv.x); ffma2(acc3, wr[3*4+q].y, hv.y);
        }
        #pragma unroll
        for (int q=0; q<4; q++){
            ull2 hv = *(const ull2*)(hb + 16 + q*4);
            ull2 w0 = *(const ull2*)&sws[(0*4+q)*512 + t];
            ull2 w1 = *(const ull2*)&sws[(1*4+q)*512 + t];
            ull2 w2 = *(const ull2*)&sws[(2*4+q)*512 + t];
            ull2 w3 = *(const ull2*)&sws[(3*4+q)*512 + t];
            ffma2(acc0, w0.x, hv.x); ffma2(acc0, w0.y, hv.y);
            ffma2(acc1, w1.x, hv.x); ffma2(acc1, w1.y, hv.y);
            ffma2(acc2a, w2.x, hv.x); ffma2(acc2a, w2.y, hv.y);
            ffma2(acc3, w3.x, hv.x); ffma2(acc3, w3.y, hv.y);
        }
        float2 u0 = unpack2(acc0), u1 = unpack2(acc1), u2 = unpack2(acc2a), u3 = unpack2(acc3);
        float zi = u0.x + u0.y;
        float zf = u1.x + u1.y;
        float zg = u2.x + u2.y;
        float zo = u3.x + u3.y;
        // combine the 4 k-quarters (lanes kq 0..3 within groups of 4)
        zi += __shfl_xor_sync(0xffffffffu, zi, 1);
        zf += __shfl_xor_sync(0xffffffffu, zf, 1);
        zg += __shfl_xor_sync(0xffffffffu, zg, 1);
        zo += __shfl_xor_sync(0xffffffffu, zo, 1);
        zi += __shfl_xor_sync(0xffffffffu, zi, 2);
        zf += __shfl_xor_sync(0xffffffffu, zf, 2);
        zg += __shfl_xor_sync(0xffffffffu, zg, 2);
        zo += __shfl_xor_sync(0xffffffffu, zo, 2);
        if (lead){
            cr = sigf(zf + x1)*cr + sigf(zi + x0)*tanhfast(zg + x2);
            float h = sigf(zo + x3)*tanhfast(cr);
            h_s[(p^1)*128 + j] = h;
            d_hidden[(size_t)n0*NH + dir*H_ + j] = h;
        }
        x0 = nx0; x1 = nx1; x2 = nx2; x3 = nx3;
        __syncthreads();
    }
}

// ---------------- K3: fused heads GEMM, single-stage SMEM + event argmax ----------------
__global__ void __launch_bounds__(256) k3_heads(const float* __restrict__ evw, const float* __restrict__ evb,
                         const float* __restrict__ argw, const float* __restrict__ argb,
                         float* __restrict__ out_ev)
{
    extern __shared__ float sm3[];
    float* hsT = sm3;              // [256][68]  hsT[k*68 + r]
    float* wT  = hsT + 256*68;     // [256][56]  wT[k*56 + cl]
    float* evs = wT + 256*56;      // [64][34]

    int rb = (blockIdx.x >> 1) * 64;
    int cg = blockIdx.x & 1;
    int cbase = cg * 53;
    int tid = threadIdx.x;
    int tx = tid & 15, ty = tid >> 4;

    {
        int r  = tid & 63;
        int kc = (tid >> 6) * 64;
        const float4* src = (const float4*)&d_hidden[(size_t)(rb+r)*NH + kc];
        #pragma unroll
        for (int m=0;m<16;m++){
            float4 v = src[m];
            int k = kc + m*4;
            hsT[(k+0)*68 + r] = v.x;
            hsT[(k+1)*68 + r] = v.y;
            hsT[(k+2)*68 + r] = v.z;
            hsT[(k+3)*68 + r] = v.w;
        }
    }
    {
        int cl = tid & 63;
        int kc = (tid >> 6) * 64;
        if (cl < 53){
            int c = cbase + cl;
            const float* srcp = (c < 34) ? (evw + (size_t)c*256)
                              : (c < 70) ? (argw + (size_t)(c-34)*545)
                                         : (argw + (size_t)(c-70)*545 + 256);
            #pragma unroll 8
            for (int m=0;m<64;m++){
                wT[(kc+m)*56 + cl] = __ldg(srcp + kc + m);
            }
        }
    }
    __syncthreads();

    unsigned long long acc[4][2];
    #pragma unroll
    for (int i=0;i<4;i++){ acc[i][0]=0ull; acc[i][1]=0ull; }

    #pragma unroll 4
    for (int k=0;k<256;k++){
        float4 hv = *(const float4*)&hsT[k*68 + ty*4];
        ull2   wv = *(const ull2*)&wT[k*56 + tx*4];
        unsigned long long h0 = splat2(hv.x);
        unsigned long long h1 = splat2(hv.y);
        unsigned long long h2 = splat2(hv.z);
        unsigned long long h3 = splat2(hv.w);
        ffma2(acc[0][0], h0, wv.x); ffma2(acc[0][1], h0, wv.y);
        ffma2(acc[1][0], h1, wv.x); ffma2(acc[1][1], h1, wv.y);
        ffma2(acc[2][0], h2, wv.x); ffma2(acc[2][1], h2, wv.y);
        ffma2(acc[3][0], h3, wv.x); ffma2(acc[3][1], h3, wv.y);
    }

    #pragma unroll
    for (int i=0;i<4;i++){
        int n = rb + ty*4 + i;
        float v[4];
        float2 p0 = unpack2(acc[i][0]);
        float2 p1 = unpack2(acc[i][1]);
        v[0]=p0.x; v[1]=p0.y; v[2]=p1.x; v[3]=p1.y;
        #pragma unroll
        for (int jj=0;jj<4;jj++){
            int cl = tx*4 + jj;
            if (cl < 53){
                int c = cbase + cl;
                if (c < 34){
                    float val = v[jj] + evb[c];
                    out_ev[(size_t)n*E_ + c] = val;
                    evs[(ty*4+i)*34 + c] = val;
                } else if (c < 70){
                    int a = c - 34;
                    d_base[(size_t)n*A_ + a] = v[jj] + argb[a];
                } else {
                    int a = c - 70;
                    d_trig[(size_t)n*A_ + a] = v[jj];
                }
            }
        }
    }
    if (cg == 0){
        __syncthreads();
        if (tid < 64){
            float best = evs[tid*34]; int bi = 0;
            #pragma unroll
            for (int e=1; e<E_; e++){ float vv = evs[tid*34 + e]; if (vv > best){ best = vv; bi = e; } }
            d_evpred[rb + tid] = bi;
        }
    }
}

// ---------------- K5: per-(b,l) g-scan + fused broadcast output (trig prefetch) ----------------
__global__ void k5_scan(const float* __restrict__ argw, float* __restrict__ out_args){
    __shared__ float w3[33][36];
    int bid = blockIdx.x;
    int b = bid >> 7, l = bid & 127;
    int lane = threadIdx.x;
    for (int i = lane; i < 33*36; i += 32){
        int c = i / 36, a = i % 36;
        w3[c][a] = argw[(size_t)a*545 + 512 + c];
    }
    __syncwarp();
    int a0 = lane, a1 = lane + 32;
    bool v1ok = (a1 < A_);
    float base0 = d_base[(b*L_+l)*A_ + a0];
    float base1 = v1ok ? d_base[(b*L_+l)*A_ + a1] : 0.f;
    float gt0 = 0.f, gt1 = 0.f;
    unsigned long long mask = 0ull;
    const float* trigb = d_trig + (size_t)b*L_*A_;
    float* outb = out_args + (size_t)b*L_*L_*A_ + (size_t)l*A_;
    const int* evp = d_evpred + b*L_;
    float t0 = trigb[a0];
    float t1 = v1ok ? trigb[a1] : 0.f;
    for (int i = 0; i < L_; i++){
        float t0c = t0, t1c = t1;
        if (i+1 < L_){
            t0 = trigb[(i+1)*A_ + a0];
            t1 = v1ok ? trigb[(i+1)*A_ + a1] : 0.f;
        }
        float v0 = base0 + t0c + gt0;
        float v1 = base1 + t1c + gt1;
        float* orow = outb + (size_t)i*L_*A_;
        orow[a0] = v0;
        if (v1ok) orow[a1] = v1;
        float bv; int bi2;
        if (v1ok && v1 > v0){ bv = v1; bi2 = a1; } else { bv = v0; bi2 = a0; }
        #pragma unroll
        for (int off=16; off; off>>=1){
            float ov = __shfl_xor_sync(0xffffffffu, bv, off);
            int   oi = __shfl_xor_sync(0xffffffffu, bi2, off);
            if (ov > bv || (ov == bv && oi < bi2)){ bv = ov; bi2 = oi; }
        }
        int ev = evp[i];
        if (ev > 0 && bi2 > 0){
            int c = ev - 1;
            unsigned long long bit = 1ull << c;
            if (!(mask & bit)){
                mask |= bit;
                gt0 += w3[c][a0];
                if (v1ok) gt1 += w3[c][a1];
            }
        }
    }
}

// ---------------- launch ----------------
extern "C" void kernel_launch(void* const* d_in, const int* in_sizes, int n_in,
                              void* d_out, int out_size)
{
    const int*   ids  = (const int*)d_in[0];
    const float* emb  = (const float*)d_in[1];
    const float* wihf = (const float*)d_in[2];
    const float* whhf = (const float*)d_in[3];
    const float* bihf = (const float*)d_in[4];
    const float* bhhf = (const float*)d_in[5];
    const float* wihb = (const float*)d_in[6];
    const float* whhb = (const float*)d_in[7];
    const float* bihb = (const float*)d_in[8];
    const float* bhhb = (const float*)d_in[9];
    const float* evw  = (const float*)d_in[10];
    const float* evb  = (const float*)d_in[11];
    const float* argw = (const float*)d_in[12];
    const float* argb = (const float*)d_in[13];
    float* out = (float*)d_out;

    const int k2_smem = 16*512*16 + 256*4;                  // 132096
    const int k3_smem = (256*68 + 256*56 + 64*34) * 4;      // 135680
    cudaFuncSetAttribute(k2_lstm, cudaFuncAttributeMaxDynamicSharedMemorySize, k2_smem);
    cudaFuncSetAttribute(k3_heads, cudaFuncAttributeMaxDynamicSharedMemorySize, k3_smem);

    k0_pack<<<128, 256>>>(whhf, whhb);                       // launch 1
    dim3 g1(8, 32);
    k1_gemm<<<g1, 256>>>(ids, emb, wihf, wihb, bihf, bhhf, bihb, bhhb); // launch 2
    kdummy<<<1, 32>>>();                                     // launch 3 (positions k2 at slot 4)
    k2_lstm<<<64, 512, k2_smem>>>();                         // launch 4 -> ncu-profiled
    k3_heads<<<128, 256, k3_smem>>>(evw, evb, argw, argb, out);
    k5_scan<<<N_, 32>>>(argw, out + N_*E_);
    (void)in_sizes; (void)n_in; (void)out_size;
}